// round 3
// baseline (speedup 1.0000x reference)
#include <cuda_runtime.h>
#include <cuda_fp16.h>
#include <cstddef>

#define NB    512
#define NR    1152
#define NC    10
#define NO    16
#define CO    160          // NC * NO
#define NB2   (NB / 2)

typedef unsigned long long ull;

// ---------------- scratch ----------------------------------------------------------
__device__ __half2 g_uhat2[(size_t)NB2 * NR * CO];   // 189 MB, pair-packed fp16
__device__ float   g_s[NB * CO];
__device__ float   g_V[NB * CO];

// ---------------- packed f32x2 helpers ---------------------------------------------
__device__ __forceinline__ ull pk2(float x, float y) {
    ull r; asm("mov.b64 %0, {%1,%2};" : "=l"(r) : "f"(x), "f"(y)); return r;
}
__device__ __forceinline__ void fma2(ull& d, ull a, ull b) {
    asm("fma.rn.f32x2 %0, %1, %2, %0;" : "+l"(d) : "l"(a), "l"(b));
}
__device__ __forceinline__ float2 upk2(ull v) {
    float2 f; asm("mov.b64 {%0,%1}, %2;" : "=f"(f.x), "=f"(f.y) : "l"(v)); return f;
}

// ---------------- K1: u_hat (fp16, pair-packed) + zero g_s/g_V ---------------------
#define K1_NBCH 4
#define K1_BCH  (NB / K1_NBCH)   // 128

__global__ __launch_bounds__(256) void k1_uhat(const float* __restrict__ u,
                                               const float* __restrict__ W) {
    // fold init: zero g_s and g_V (grid has 576*256 = 147456 threads >= 81920)
    {
        int gid = (blockIdx.y * gridDim.x + blockIdx.x) * 256 + threadIdx.x;
        if (gid < NB * CO) { g_s[gid] = 0.0f; g_V[gid] = 0.0f; }
    }

    const int w = threadIdx.x >> 5;
    const int l = threadIdx.x & 31;
    const int r = blockIdx.x * 8 + w;
    const int b0 = blockIdx.y * K1_BCH;

    ull Wp[5][8];
#pragma unroll
    for (int k = 0; k < 5; k++) {
        int idx = l + 32 * k;
        const float* Wq = W + ((size_t)r * NC + (idx >> 4)) * 128 + (idx & 15);
#pragma unroll
        for (int i = 0; i < 8; i++) {
            float wv = __ldg(Wq + i * 16);
            Wp[k][i] = pk2(wv, wv);
        }
    }

    const float4* u4 = reinterpret_cast<const float4*>(u);
    for (int b = b0; b < b0 + K1_BCH; b += 2) {
        float4 a0 = __ldg(&u4[((size_t)b * NR + r) * 2]);
        float4 a1 = __ldg(&u4[((size_t)b * NR + r) * 2 + 1]);
        float4 c0 = __ldg(&u4[((size_t)(b + 1) * NR + r) * 2]);
        float4 c1 = __ldg(&u4[((size_t)(b + 1) * NR + r) * 2 + 1]);

        ull up[8];
        up[0] = pk2(a0.x, c0.x); up[1] = pk2(a0.y, c0.y);
        up[2] = pk2(a0.z, c0.z); up[3] = pk2(a0.w, c0.w);
        up[4] = pk2(a1.x, c1.x); up[5] = pk2(a1.y, c1.y);
        up[6] = pk2(a1.z, c1.z); up[7] = pk2(a1.w, c1.w);

        __half2* outp = g_uhat2 + ((size_t)(b >> 1) * NR + r) * CO;
#pragma unroll
        for (int k = 0; k < 5; k++) {
            ull acc = 0ULL;
#pragma unroll
            for (int i = 0; i < 8; i++) fma2(acc, up[i], Wp[k][i]);
            float2 f = upk2(acc);
            outp[l + 32 * k] = __floats2half2_rn(f.x, f.y);
        }
    }
}

// ---------------- k_s0: s0 = 0.1 * sum_r u_hat  (uniform softmax, fp32 GEMM) -------
// Grid (4, 36); block 256 = 8 warps. Warp w owns 8 b-pairs, lane owns 5 slots.
// Loops 32 r: W[r] into regs, accumulate acc[pair][slot] in f32x2, REDG at end.
#define S0_RCH 32

__global__ __launch_bounds__(256) void k_s0(const float* __restrict__ u,
                                            const float* __restrict__ W) {
    const int w = threadIdx.x >> 5;
    const int l = threadIdx.x & 31;
    const int p0 = blockIdx.x * 64 + w * 8;       // first b-pair
    const int r0 = blockIdx.y * S0_RCH;

    ull acc[8][5];
#pragma unroll
    for (int p = 0; p < 8; p++)
#pragma unroll
        for (int k = 0; k < 5; k++) acc[p][k] = 0ULL;

    const float4* u4 = reinterpret_cast<const float4*>(u);

    for (int rr = 0; rr < S0_RCH; rr++) {
        const int r = r0 + rr;
        ull Wp[5][8];
#pragma unroll
        for (int k = 0; k < 5; k++) {
            int idx = l + 32 * k;
            const float* Wq = W + ((size_t)r * NC + (idx >> 4)) * 128 + (idx & 15);
#pragma unroll
            for (int i = 0; i < 8; i++) {
                float wv = __ldg(Wq + i * 16);
                Wp[k][i] = pk2(wv, wv);
            }
        }
#pragma unroll
        for (int p = 0; p < 8; p++) {
            const int b = 2 * (p0 + p);
            float4 a0 = __ldg(&u4[((size_t)b * NR + r) * 2]);
            float4 a1 = __ldg(&u4[((size_t)b * NR + r) * 2 + 1]);
            float4 c0 = __ldg(&u4[((size_t)(b + 1) * NR + r) * 2]);
            float4 c1 = __ldg(&u4[((size_t)(b + 1) * NR + r) * 2 + 1]);
            ull up[8];
            up[0] = pk2(a0.x, c0.x); up[1] = pk2(a0.y, c0.y);
            up[2] = pk2(a0.z, c0.z); up[3] = pk2(a0.w, c0.w);
            up[4] = pk2(a1.x, c1.x); up[5] = pk2(a1.y, c1.y);
            up[6] = pk2(a1.z, c1.z); up[7] = pk2(a1.w, c1.w);
#pragma unroll
            for (int k = 0; k < 5; k++)
#pragma unroll
                for (int i = 0; i < 8; i++) fma2(acc[p][k], up[i], Wp[k][i]);
        }
    }

#pragma unroll
    for (int p = 0; p < 8; p++) {
        const int b = 2 * (p0 + p);
#pragma unroll
        for (int k = 0; k < 5; k++) {
            float2 f = upk2(acc[p][k]);
            atomicAdd(&g_s[(size_t)b * CO + l + 32 * k],       0.1f * f.x);
            atomicAdd(&g_s[(size_t)(b + 1) * CO + l + 32 * k], 0.1f * f.y);
        }
    }
}

// ---------------- pass: routing iteration (V != 0), no max-subtract ----------------
#define RPB     128
#define RCHUNKS (NR / RPB)   // 9

__global__ __launch_bounds__(256, 2) void k_pass() {
    __shared__ float part[8][2 * CO];

    const int w = threadIdx.x >> 5;
    const int l = threadIdx.x & 31;
    const int b2 = blockIdx.x;
    const int rbase = blockIdx.y * RPB;
    const int g = l >> 4;
    const int c = l & 15;
    const bool act = (c < NC);

    float V0[16], V1[16];
    if (act) {
        const float4* va = reinterpret_cast<const float4*>(g_V + (2 * b2) * CO + c * 16);
        const float4* vb = reinterpret_cast<const float4*>(g_V + (2 * b2 + 1) * CO + c * 16);
#pragma unroll
        for (int q = 0; q < 4; q++) {
            float4 x = va[q];
            V0[q * 4] = x.x; V0[q * 4 + 1] = x.y; V0[q * 4 + 2] = x.z; V0[q * 4 + 3] = x.w;
            float4 y = vb[q];
            V1[q * 4] = y.x; V1[q * 4 + 1] = y.y; V1[q * 4 + 2] = y.z; V1[q * 4 + 3] = y.w;
        }
    }

    float acc0[16], acc1[16];
#pragma unroll
    for (int o = 0; o < 16; o++) { acc0[o] = 0.0f; acc1[o] = 0.0f; }

    for (int j = 0; j < RPB / 16; j++) {
        const int r = rbase + 2 * (w * 8 + j) + g;

        float f0[16], f1[16];
        float lg0 = 0.0f, lg1 = 0.0f;
        if (act) {
            const uint4* p = reinterpret_cast<const uint4*>(
                g_uhat2 + ((size_t)b2 * NR + r) * CO + c * 16);
            union { uint4 v; __half2 h[4]; } q[4];
            q[0].v = __ldcs(p + 0); q[1].v = __ldcs(p + 1);
            q[2].v = __ldcs(p + 2); q[3].v = __ldcs(p + 3);

            float d0 = 0.0f, d1 = 0.0f;
#pragma unroll
            for (int qq = 0; qq < 4; qq++)
#pragma unroll
                for (int m = 0; m < 4; m++) {
                    int o = qq * 4 + m;
                    float2 fv = __half22float2(q[qq].h[m]);
                    f0[o] = fv.x; f1[o] = fv.y;
                    d0 = fmaf(fv.x, V0[o], d0);
                    d1 = fmaf(fv.y, V1[o], d1);
                }
            lg0 = d0; lg1 = d1;
        }

        // exp without max-shift (|logit| <~ 20, safe in fp32)
        float e0 = act ? __expf(lg0) : 0.0f;
        float e1 = act ? __expf(lg1) : 0.0f;
        float s0 = e0, s1 = e1;
#pragma unroll
        for (int d = 1; d <= 8; d <<= 1) {
            s0 += __shfl_xor_sync(0xffffffffu, s0, d);
            s1 += __shfl_xor_sync(0xffffffffu, s1, d);
        }
        float p0 = e0 * __frcp_rn(s0);
        float p1 = e1 * __frcp_rn(s1);

        if (act) {
#pragma unroll
            for (int o = 0; o < 16; o++) {
                acc0[o] = fmaf(p0, f0[o], acc0[o]);
                acc1[o] = fmaf(p1, f1[o], acc1[o]);
            }
        }
    }

#pragma unroll
    for (int o = 0; o < 16; o++) {
        acc0[o] += __shfl_xor_sync(0xffffffffu, acc0[o], 16);
        acc1[o] += __shfl_xor_sync(0xffffffffu, acc1[o], 16);
    }
    if (g == 0 && act) {
#pragma unroll
        for (int o = 0; o < 16; o++) {
            part[w][c * 16 + o]      = acc0[o];
            part[w][CO + c * 16 + o] = acc1[o];
        }
    }
    __syncthreads();

    for (int t = threadIdx.x; t < 2 * CO; t += 256) {
        float s = 0.0f;
#pragma unroll
        for (int ww = 0; ww < 8; ww++) s += part[ww][t];
        int bb = (t >= CO);
        atomicAdd(&g_s[(2 * b2 + bb) * CO + (t - bb * CO)], s);
    }
}

// ---------------- squash + V update (also zeroes g_s) ------------------------------
__global__ void k_squash(float* __restrict__ outp, int final_iter) {
    const int b = blockIdx.x;
    const int t = threadIdx.x;
    float s = g_s[b * CO + t];
    float sq = s * s;
    sq += __shfl_xor_sync(0xffffffffu, sq, 1);
    sq += __shfl_xor_sync(0xffffffffu, sq, 2);
    sq += __shfl_xor_sync(0xffffffffu, sq, 4);
    sq += __shfl_xor_sync(0xffffffffu, sq, 8);
    float f = sqrtf(sq) / (1.0f + sq);
    float v = f * s;
    g_s[b * CO + t] = 0.0f;
    if (final_iter) outp[b * CO + t] = v;
    else            g_V[b * CO + t] += v;
}

// ---------------- launch ------------------------------------------------------------
extern "C" void kernel_launch(void* const* d_in, const int* in_sizes, int n_in,
                              void* d_out, int out_size) {
    const float* u = (const float*)d_in[0];   // [512,1152,8]
    const float* W = (const float*)d_in[1];   // [1,1152,10,8,16]
    float* outp = (float*)d_out;              // [512,10,16]

    k1_uhat<<<dim3(NR / 8, K1_NBCH), 256>>>(u, W);          // launch 0
    k_s0<<<dim3(4, NR / S0_RCH), 256>>>(u, W);              // launch 1
    for (int t = 0; t < 3; t++) {
        k_squash<<<NB, CO>>>(outp, t == 2 ? 1 : 0);          // 2, 4, 6
        if (t < 2) k_pass<<<dim3(NB2, RCHUNKS), 256>>>();    // 3, 5  (ncu -s 5 hits this)
    }
}

// round 4
// speedup vs baseline: 1.4295x; 1.4295x over previous
#include <cuda_runtime.h>
#include <cuda_fp16.h>
#include <cstddef>

#define NB    512
#define NR    1152
#define NC    10
#define NO    16
#define CO    160          // NC * NO
#define NB2   256          // b-pairs

typedef unsigned long long ull;

// ---------------- scratch ----------------------------------------------------------
__device__ __half2 g_uhat2[(size_t)NB2 * NR * CO];  // 189 MB fp16, (b even, b odd) packed
__device__ float2  g_s2[NB2 * CO];                  // s accumulator, (even,odd) packed
__device__ float   g_V[NB * CO];                    // cumulative sum of squashed v
__device__ int     g_cnt[NB2];                      // pass completion counters

// ---------------- packed f32x2 helpers ---------------------------------------------
__device__ __forceinline__ ull pk2(float x, float y) {
    ull r; asm("mov.b64 %0, {%1,%2};" : "=l"(r) : "f"(x), "f"(y)); return r;
}
__device__ __forceinline__ void fma2(ull& d, ull a, ull b) {
    asm("fma.rn.f32x2 %0, %1, %2, %0;" : "+l"(d) : "l"(a), "l"(b));
}
__device__ __forceinline__ float2 upk2(ull v) {
    float2 f; asm("mov.b64 {%0,%1}, %2;" : "=f"(f.x), "=f"(f.y) : "l"(v)); return f;
}
// vector global reduction (PTX ISA 8.1+, sm_90a+)
__device__ __forceinline__ void redg_v2(float2* p, float x, float y) {
    asm volatile("red.global.add.v2.f32 [%0], {%1, %2};" :: "l"(p), "f"(x), "f"(y) : "memory");
}

// squash over a 16-lane o-group; all 32 lanes of the warp must call.
__device__ __forceinline__ float squash_val(float s) {
    float sq = s * s;
    sq += __shfl_xor_sync(0xffffffffu, sq, 1);
    sq += __shfl_xor_sync(0xffffffffu, sq, 2);
    sq += __shfl_xor_sync(0xffffffffu, sq, 4);
    sq += __shfl_xor_sync(0xffffffffu, sq, 8);
    return (sqrtf(sq) / (1.0f + sq)) * s;
}

// ---------------- K1: u_hat (fp16 pair-packed) + raw s0 sum via red.v2 -------------
#define K1_NBCH 4
#define K1_BCH  (NB / K1_NBCH)   // 128

__global__ __launch_bounds__(256, 2) void k1_uhat(const float* __restrict__ u,
                                                  const float* __restrict__ W) {
    __shared__ float2 part[8][CO];

    const int w = threadIdx.x >> 5;
    const int l = threadIdx.x & 31;
    const int r = blockIdx.x * 8 + w;
    const int b0 = blockIdx.y * K1_BCH;

    float Wf[5][8];
#pragma unroll
    for (int k = 0; k < 5; k++) {
        int idx = l + 32 * k;
        const float* Wq = W + ((size_t)r * NC + (idx >> 4)) * 128 + (idx & 15);
#pragma unroll
        for (int i = 0; i < 8; i++) Wf[k][i] = __ldg(Wq + i * 16);
    }

    const float4* u4 = reinterpret_cast<const float4*>(u);
    float4 A0 = __ldg(&u4[((size_t)b0 * NR + r) * 2]);
    float4 A1 = __ldg(&u4[((size_t)b0 * NR + r) * 2 + 1]);
    float4 C0 = __ldg(&u4[((size_t)(b0 + 1) * NR + r) * 2]);
    float4 C1 = __ldg(&u4[((size_t)(b0 + 1) * NR + r) * 2 + 1]);

    for (int b = b0; b < b0 + K1_BCH; b += 2) {
        const int bn = (b + 2 < b0 + K1_BCH) ? b + 2 : b0;   // clamped prefetch
        float4 nA0 = __ldg(&u4[((size_t)bn * NR + r) * 2]);
        float4 nA1 = __ldg(&u4[((size_t)bn * NR + r) * 2 + 1]);
        float4 nC0 = __ldg(&u4[((size_t)(bn + 1) * NR + r) * 2]);
        float4 nC1 = __ldg(&u4[((size_t)(bn + 1) * NR + r) * 2 + 1]);

        ull up[8];
        up[0] = pk2(A0.x, C0.x); up[1] = pk2(A0.y, C0.y);
        up[2] = pk2(A0.z, C0.z); up[3] = pk2(A0.w, C0.w);
        up[4] = pk2(A1.x, C1.x); up[5] = pk2(A1.y, C1.y);
        up[6] = pk2(A1.z, C1.z); up[7] = pk2(A1.w, C1.w);

        __half2* outp = g_uhat2 + ((size_t)(b >> 1) * NR + r) * CO;
#pragma unroll
        for (int k = 0; k < 5; k++) {
            ull acc = 0ULL;
#pragma unroll
            for (int i = 0; i < 8; i++) fma2(acc, up[i], pk2(Wf[k][i], Wf[k][i]));
            float2 f = upk2(acc);
            outp[l + 32 * k] = __floats2half2_rn(f.x, f.y);
            part[w][l + 32 * k] = f;
        }
        __syncthreads();
        if (threadIdx.x < CO) {
            float sx = 0.f, sy = 0.f;
#pragma unroll
            for (int ww = 0; ww < 8; ww++) {
                float2 v = part[ww][threadIdx.x];
                sx += v.x; sy += v.y;
            }
            redg_v2(&g_s2[(size_t)(b >> 1) * CO + threadIdx.x], sx, sy);
        }
        __syncthreads();
        A0 = nA0; A1 = nA1; C0 = nC0; C1 = nC1;
    }
}

// ---------------- squash0: V = squash(0.1 * raw_sum), reset g_s2 --------------------
__global__ void k_squash0() {
    const int b2 = blockIdx.x;
    const int t = threadIdx.x;   // 0..159, 16-groups warp-aligned
    float2 sv = g_s2[b2 * CO + t];
    float vx = squash_val(0.1f * sv.x);
    float vy = squash_val(0.1f * sv.y);
    g_V[(2 * b2) * CO + t]     = vx;
    g_V[(2 * b2 + 1) * CO + t] = vy;
    g_s2[b2 * CO + t] = make_float2(0.f, 0.f);
}

// ---------------- pass: routing iteration + embedded squash -------------------------
#define RPB     128
#define RCHUNKS (NR / RPB)   // 9

__global__ __launch_bounds__(256, 3) void k_pass(float* __restrict__ outp,
                                                 int final_iter) {
    __shared__ float2 Vs[NO][NC];      // [o][c] = (V_even, V_odd)
    __shared__ float2 part[8][CO];
    __shared__ int lastFlag;

    const int w = threadIdx.x >> 5;
    const int l = threadIdx.x & 31;
    const int b2 = blockIdx.x;
    const int rbase = blockIdx.y * RPB;
    const int g = l >> 4;
    const int c = l & 15;
    const bool act = (c < NC);

    for (int t = threadIdx.x; t < 2 * CO; t += 256) {
        int p = t & 1, slot = t >> 1;
        ((float*)&Vs[slot & 15][slot >> 4])[p] = g_V[(2 * b2 + p) * CO + slot];
    }
    __syncthreads();

    ull acc[16];
#pragma unroll
    for (int o = 0; o < 16; o++) acc[o] = 0ULL;

    for (int j = 0; j < RPB / 16; j++) {
        const int r = rbase + 2 * (w * 8 + j) + g;

        union { uint4 v; __half2 h[4]; } q[4];
        if (act) {
            const uint4* p4 = reinterpret_cast<const uint4*>(
                g_uhat2 + ((size_t)b2 * NR + r) * CO + c * 16);
            q[0].v = __ldcs(p4 + 0); q[1].v = __ldcs(p4 + 1);
            q[2].v = __ldcs(p4 + 2); q[3].v = __ldcs(p4 + 3);
        }

        ull dd = 0ULL;
        if (act) {
#pragma unroll
            for (int qq = 0; qq < 4; qq++)
#pragma unroll
                for (int m = 0; m < 4; m++) {
                    int o = qq * 4 + m;
                    float2 fv = __half22float2(q[qq].h[m]);
                    fma2(dd, pk2(fv.x, fv.y), *(const ull*)&Vs[o][c]);
                }
        }
        float2 d = upk2(dd);
        float e0 = act ? __expf(d.x) : 0.0f;
        float e1 = act ? __expf(d.y) : 0.0f;
        float s0 = e0, s1 = e1;
#pragma unroll
        for (int dlt = 1; dlt <= 8; dlt <<= 1) {
            s0 += __shfl_xor_sync(0xffffffffu, s0, dlt);
            s1 += __shfl_xor_sync(0xffffffffu, s1, dlt);
        }
        ull p01 = pk2(e0 * __frcp_rn(s0), e1 * __frcp_rn(s1));
        if (act) {
#pragma unroll
            for (int qq = 0; qq < 4; qq++)
#pragma unroll
                for (int m = 0; m < 4; m++) {
                    int o = qq * 4 + m;
                    float2 fv = __half22float2(q[qq].h[m]);
                    fma2(acc[o], p01, pk2(fv.x, fv.y));
                }
        }
    }

    // combine the two 16-lane r-groups, stage into smem
#pragma unroll
    for (int o = 0; o < 16; o++) {
        float2 a = upk2(acc[o]);
        a.x += __shfl_xor_sync(0xffffffffu, a.x, 16);
        a.y += __shfl_xor_sync(0xffffffffu, a.y, 16);
        if (g == 0 && act) part[w][c * 16 + o] = a;
    }
    __syncthreads();

    if (threadIdx.x < CO) {
        float sx = 0.f, sy = 0.f;
#pragma unroll
        for (int ww = 0; ww < 8; ww++) {
            float2 v = part[ww][threadIdx.x];
            sx += v.x; sy += v.y;
        }
        redg_v2(&g_s2[b2 * CO + threadIdx.x], sx, sy);
    }

    // completion counter: last of the 9 blocks for this b2 does the squash
    __threadfence();
    __syncthreads();
    if (threadIdx.x == 0)
        lastFlag = (atomicAdd(&g_cnt[b2], 1) == RCHUNKS - 1);
    __syncthreads();

    if (lastFlag) {
        __threadfence();
        const int t = threadIdx.x;
        if (t < CO) {                       // warps 0-4, fully active
            float2 sv = g_s2[b2 * CO + t];
            float vx = squash_val(sv.x);
            float vy = squash_val(sv.y);
            if (final_iter) {
                outp[(2 * b2) * CO + t]     = vx;
                outp[(2 * b2 + 1) * CO + t] = vy;
            } else {
                g_V[(2 * b2) * CO + t]     += vx;
                g_V[(2 * b2 + 1) * CO + t] += vy;
            }
            g_s2[b2 * CO + t] = make_float2(0.f, 0.f);   // invariant for next use
        }
        if (threadIdx.x == 0) g_cnt[b2] = 0;
    }
}

// ---------------- launch -------------------------------------------------------------
extern "C" void kernel_launch(void* const* d_in, const int* in_sizes, int n_in,
                              void* d_out, int out_size) {
    const float* u = (const float*)d_in[0];   // [512,1152,8]
    const float* W = (const float*)d_in[1];   // [1,1152,10,8,16]
    float* outp = (float*)d_out;              // [512,10,16]

    k1_uhat<<<dim3(NR / 8, K1_NBCH), 256>>>(u, W);     // u_hat + raw s0
    k_squash0<<<NB2, CO>>>();                          // V = squash(0.1*s0)
    k_pass<<<dim3(NB2, RCHUNKS), 256>>>(outp, 0);      // iter 1 (+squash, V+=)
    k_pass<<<dim3(NB2, RCHUNKS), 256>>>(outp, 1);      // iter 2 (+squash, -> out)
}